// round 5
// baseline (speedup 1.0000x reference)
#include <cuda_runtime.h>
#include <math.h>

#define QDIM 1000
#define CDIM 80
#define QC   80000
#define KSEL 300
#define CAP  4096
#define CAP2 2048
#define SAMP_RANK 40
#define NBIN 2048
#define MAXB 512
#define NPART 4                         // stream CTAs per batch
#define PART_F4 (QC / 4 / NPART)        // 5000 float4 per part

// global scratch (allowed: __device__ arrays, no allocation)
__device__ unsigned long long g_cand[MAXB * CAP];   // 16 MB
__device__ unsigned g_cnt[MAXB];
__device__ unsigned g_cut[MAXB];

// Monotone order-preserving map f32 -> u32.
__device__ __forceinline__ unsigned fkey(float x) {
    unsigned u = __float_as_uint(x);
    return u ^ (((unsigned)((int)u >> 31)) | 0x80000000u);
}

// sigmoid-bits -> refine bucket (0 = best). 2048-ulp buckets.
__device__ __forceinline__ unsigned sig_bucket(unsigned sb) {
    int d = (int)(0x3F800000u - sb);
    if (d <= 0) return 0u;
    unsigned bkt = (unsigned)d >> 11;
    return bkt > 2047u ? 2047u : bkt;
}

// warp-0 segmented scan over hist[2048]: smallest bucket index with
// cumulative count >= rank. (bucket 0 = highest values)
__device__ __forceinline__ void scan_rank(const unsigned* hist, unsigned rank,
                                          unsigned* out_bucket, int lane) {
    unsigned s = 0;
    #pragma unroll 1
    for (int i = 0; i < 64; ++i)
        s += hist[lane * 64 + ((i + lane) & 63)];
    unsigned sc = s;
    #pragma unroll
    for (int o = 1; o < 32; o <<= 1) {
        unsigned t = __shfl_up_sync(0xffffffffu, sc, o);
        if (lane >= o) sc += t;
    }
    unsigned vote = __ballot_sync(0xffffffffu, sc >= rank);
    int seg = vote ? (__ffs(vote) - 1) : 31;
    if (lane == seg) {
        unsigned excl = sc - s;
        int cb = seg * 64 + 63;
        for (int i = seg * 64; i < seg * 64 + 64; ++i) {
            excl += hist[i];
            if (excl >= rank) { cb = i; break; }
        }
        *out_bucket = (unsigned)cb;
    }
}

// ============================================================================
// Kernel 0: per-batch rough cut from a 2048-point sampled histogram.
// cut ~ rank-40-of-2048 => survivors ~1560 +- 250 (>=300 at ~5sigma, <=CAP
// at ~10sigma).
// ============================================================================
__global__ void __launch_bounds__(256)
k_cut(const float* __restrict__ logits)
{
    __shared__ unsigned hist[NBIN];
    __shared__ unsigned s_cutb;
    const int b = blockIdx.x, tid = threadIdx.x;
    const float* lg = logits + (size_t)b * QC;

    #pragma unroll
    for (int k = 0; k < NBIN / 256; ++k) hist[tid + k * 256] = 0;
    __syncthreads();
    // 16 coalesced runs of 128 consecutive floats (iid data -> valid sample)
    #pragma unroll
    for (int k = 0; k < 8; ++k) {
        int s = tid + k * 256;
        int pos = (s >> 7) * 5000 + (s & 127);
        atomicAdd(&hist[2047u - (fkey(__ldg(lg + pos)) >> 21)], 1u);
    }
    __syncthreads();
    if (tid < 32) scan_rank(hist, SAMP_RANK, &s_cutb, tid);
    __syncthreads();
    if (tid == 0) {
        g_cut[b] = (2047u - s_cutb) << 21;
        g_cnt[b] = 0;
    }
}

// ============================================================================
// Kernel A: pure streaming filter. 4 CTAs per batch, 256 threads, no smem
// (occ 8). Survivors exit via warp-aggregated global atomics (~50/warp-CTA).
// ============================================================================
__global__ void __launch_bounds__(256)
k_stream(const float* __restrict__ logits)
{
    const int b    = blockIdx.x >> 2;
    const int part = blockIdx.x & 3;
    const int tid  = threadIdx.x;
    const int lane = tid & 31;
    const unsigned cut = g_cut[b];
    const float4* lg4 = (const float4*)(logits + (size_t)b * QC) + part * PART_F4;
    unsigned long long* cb = g_cand + (size_t)b * CAP;

    // fixed trip count, all threads stay resident -> full-mask ballots
    #pragma unroll 4
    for (int it = 0; it < (PART_F4 + 255) / 256; ++it) {
        int i = it * 256 + tid;
        bool inb = (i < PART_F4);
        float4 v = inb ? lg4[i] : make_float4(-1e30f, -1e30f, -1e30f, -1e30f);
        unsigned base = (unsigned)((part * PART_F4 + i) * 4);
        float xs[4] = {v.x, v.y, v.z, v.w};
        #pragma unroll
        for (int j = 0; j < 4; ++j) {
            bool pred = inb && (fkey(xs[j]) >= cut);
            unsigned m = __ballot_sync(0xffffffffu, pred);
            if (m) {
                int leader = __ffs(m) - 1;
                unsigned p0 = 0;
                if (lane == leader) p0 = atomicAdd(&g_cnt[b], (unsigned)__popc(m));
                p0 = __shfl_sync(0xffffffffu, p0, leader);
                if (pred) {
                    unsigned p = p0 + __popc(m & ((1u << lane) - 1u));
                    if (p < CAP)
                        cb[p] = ((unsigned long long)__float_as_uint(xs[j]) << 32)
                                | (base + j);
                }
            }
        }
    }
}

// ============================================================================
// Kernel B: selection on ~1560 L2-hot candidates per batch.
// Composite = (f32 sigmoid bits << 32) | ~index : matches jax.lax.top_k
// (sigmoid in double rounded to f32; ties break toward lower index).
// ============================================================================
__global__ void __launch_bounds__(1024, 2)
k_select(const float* __restrict__ boxes,
         const float* __restrict__ sizes,
         float* __restrict__ out, int B)
{
    __shared__ unsigned long long cand2[CAP2];  // 16 KB
    __shared__ unsigned hist[NBIN];             //  8 KB
    __shared__ unsigned s_cutb, s_cnt2;

    const int b = blockIdx.x, tid = threadIdx.x;
    unsigned long long* cb = g_cand + (size_t)b * CAP;
    const unsigned cnt = min(g_cnt[b], (unsigned)CAP);

    hist[tid] = 0; hist[tid + 1024] = 0;
    if (tid == 0) s_cnt2 = 0;
    __syncthreads();

    // Phase 1: sigmoid composite (write back to global, L2-hot) + refine hist.
    for (unsigned i = tid; i < cnt; i += 1024) {
        unsigned long long cc = cb[i];
        float x = __uint_as_float((unsigned)(cc >> 32));
        unsigned idx = (unsigned)cc;
        float sf = (float)(1.0 / (1.0 + exp(-(double)x)));
        unsigned sb = __float_as_uint(sf);
        cb[i] = ((unsigned long long)sb << 32) | (~idx);
        atomicAdd(&hist[sig_bucket(sb)], 1u);
    }
    __syncthreads();

    // Phase 2: exact-bucket rank-300 cut (tie groups share buckets -> safe).
    if (tid < 32) scan_rank(hist, KSEL, &s_cutb, tid);
    __syncthreads();
    const unsigned cutb2 = s_cutb;

    // Phase 3: refined compaction (~300-360 survivors).
    for (unsigned i = tid; i < cnt; i += 1024) {
        unsigned long long cc = cb[i];
        if (sig_bucket((unsigned)(cc >> 32)) <= cutb2) {
            unsigned p = atomicAdd(&s_cnt2, 1u);
            if (p < CAP2) cand2[p] = cc;
        }
    }
    __syncthreads();
    const unsigned cnt2 = min(s_cnt2, (unsigned)CAP2);

    // Phase 4: bitonic sort (descending), hybrid warp/block syncs.
    unsigned M = 512; while (M < cnt2) M <<= 1;
    for (unsigned i = cnt2 + tid; i < M; i += 1024) cand2[i] = 0ull;
    __syncthreads();
    const bool wok = (M <= 1024u);
    for (unsigned k = 2; k <= M; k <<= 1) {
        for (unsigned j = k >> 1; j > 0; j >>= 1) {
            for (unsigned i = tid; i < M; i += 1024) {
                unsigned ixj = i ^ j;
                if (ixj > i) {
                    unsigned long long a = cand2[i], c = cand2[ixj];
                    bool up = ((i & k) == 0);
                    if (up ? (a < c) : (a > c)) { cand2[i] = c; cand2[ixj] = a; }
                }
            }
            unsigned jn = (j > 1) ? (j >> 1) : k;
            if (!wok || j >= 32 || jn >= 32) __syncthreads();
            else __syncwarp();
        }
    }

    // Phase 5: emit top-300 (labels | boxes | scores).
    if (tid < KSEL) {
        unsigned long long cc = cand2[tid];
        unsigned sig = (unsigned)(cc >> 32);
        unsigned idx = ~(unsigned)cc;
        if (idx >= QC) idx = 0;                 // safety (unreachable)
        unsigned q   = idx / CDIM;
        unsigned cls = idx - q * CDIM;

        float4 bx = ((const float4*)boxes)[(size_t)b * QDIM + q];
        float W = sizes[2 * b], H = sizes[2 * b + 1];

        int BK = B * KSEL;
        int o  = b * KSEL + tid;
        out[o] = (float)cls;                                   // labels
        float x1 = (bx.x - 0.5f * bx.z) * W;
        float y1 = (bx.y - 0.5f * bx.w) * H;
        float x2 = (bx.x + 0.5f * bx.z) * W;
        float y2 = (bx.y + 0.5f * bx.w) * H;
        ((float4*)(out + BK))[o] = make_float4(x1, y1, x2, y2); // boxes
        out[5 * BK + o] = __uint_as_float(sig);                 // scores
    }
}

extern "C" void kernel_launch(void* const* d_in, const int* in_sizes, int n_in,
                              void* d_out, int out_size) {
    const float* logits = (const float*)d_in[0];
    const float* boxes  = (const float*)d_in[1];
    const float* sizes  = (const float*)d_in[2];
    int B = in_sizes[0] / QC;
    if (B > MAXB) B = MAXB;
    k_cut<<<B, 256>>>(logits);
    k_stream<<<B * NPART, 256>>>(logits);
    k_select<<<B, 1024>>>(boxes, sizes, (float*)d_out, B);
}

// round 9
// speedup vs baseline: 2.3203x; 2.3203x over previous
#include <cuda_runtime.h>
#include <math.h>

#define QDIM 1000
#define CDIM 80
#define QC   80000
#define NF4  (QC / 4)       // 20000
#define KSEL 300
#define NTHREADS 1024
#define NWARP 32
#define WSEG 256            // slots per warp segment (worst-case mean ~115)
#define CAP  (NWARP * WSEG) // 8192
#define CAP2 2048
#define SAMP_RANK 40
#define NBIN 2048

// Monotone order-preserving map f32 -> u32 (total order, handles negatives).
__device__ __forceinline__ unsigned fkey(float x) {
    unsigned u = __float_as_uint(x);
    return u ^ (((unsigned)((int)u >> 31)) | 0x80000000u);
}

// sigmoid-bits -> refine bucket (0 = best). 2048-ulp buckets.
__device__ __forceinline__ unsigned sig_bucket(unsigned sb) {
    int d = (int)(0x3F800000u - sb);
    if (d <= 0) return 0u;
    unsigned bkt = (unsigned)d >> 11;
    return bkt > 2047u ? 2047u : bkt;
}

// warp-0 segmented scan over hist[2048]: smallest bucket with cumcount>=rank.
__device__ __forceinline__ void scan_rank(const unsigned* hist, unsigned rank,
                                          unsigned* out_bucket, int lane) {
    unsigned s = 0;
    #pragma unroll 1
    for (int i = 0; i < 64; ++i)
        s += hist[lane * 64 + ((i + lane) & 63)];
    unsigned sc = s;
    #pragma unroll
    for (int o = 1; o < 32; o <<= 1) {
        unsigned t = __shfl_up_sync(0xffffffffu, sc, o);
        if (lane >= o) sc += t;
    }
    unsigned vote = __ballot_sync(0xffffffffu, sc >= rank);
    int seg = vote ? (__ffs(vote) - 1) : 31;
    if (lane == seg) {
        unsigned excl = sc - s;
        int cb = seg * 64 + 63;
        for (int i = seg * 64; i < seg * 64 + 64; ++i) {
            excl += hist[i];
            if (excl >= rank) { cb = i; break; }
        }
        *out_bucket = (unsigned)cb;
    }
}

__global__ void __launch_bounds__(NTHREADS, 2)
rtdetr_post_kernel(const float* __restrict__ logits,
                   const float* __restrict__ boxes,
                   const float* __restrict__ sizes,
                   float* __restrict__ out, int B)
{
    __shared__ unsigned long long cand[CAP];    // 64 KB, per-warp segments
    __shared__ unsigned long long cand2[CAP2];  // 16 KB
    __shared__ unsigned hist[NBIN];             //  8 KB
    __shared__ unsigned wcnts[NWARP];
    __shared__ unsigned s_cutb, s_cnt2;

    const int b    = blockIdx.x;
    const int tid  = threadIdx.x;
    const int wid  = tid >> 5;
    const int lane = tid & 31;
    const float* lg = logits + (size_t)b * QC;

    // ---------------- Phase 0a: sampled histogram of fkey top-11-bits.
    hist[tid] = 0; hist[tid + NTHREADS] = 0;
    if (tid == 0) s_cnt2 = 0;
    __syncthreads();
    // 16 coalesced runs of 128 consecutive floats (iid data -> valid sample)
    {
        int pos0 = (tid >> 7) * 5000 + (tid & 127);
        int s2   = tid + NTHREADS;
        int pos1 = (s2 >> 7) * 5000 + (s2 & 127);
        atomicAdd(&hist[2047u - (fkey(__ldg(lg + pos0)) >> 21)], 1u);
        atomicAdd(&hist[2047u - (fkey(__ldg(lg + pos1)) >> 21)], 1u);
    }
    __syncthreads();

    // ---------------- Phase 0b: rough cut = ~rank-40-of-2048 sample.
    // Bucket edges are coarse (4/binade near z~2): worst-case true survivors
    // ~3700 per batch (~115/warp) -> WSEG=256 is ~13 sigma against overflow.
    if (tid < 32) scan_rank(hist, SAMP_RANK, &s_cutb, tid);
    __syncthreads();
    const unsigned cut = (2047u - s_cutb) << 21;   // keys >= cut survive
    hist[tid] = 0; hist[tid + NTHREADS] = 0;       // re-zero for refine pass

    // ---------------- Phase 1: stream. Zero atomics: per-warp segment in
    // cand[] + uniform register count, ballot/popc compaction. Loads are
    // explicitly batched (4x LDG.128) before any convergence point -> MLP=4.
    const float4* lg4 = (const float4*)lg;
    const unsigned wbase = (unsigned)wid * WSEG;
    const unsigned lmask = (1u << lane) - 1u;
    unsigned wcnt = 0;                              // uniform across warp
    #pragma unroll 1
    for (int it = 0; it < 5; ++it) {
        int i0 = it * (4 * NTHREADS) + tid;
        float4 v[4];
        #pragma unroll
        for (int u = 0; u < 4; ++u) {
            int i = i0 + u * NTHREADS;
            v[u] = (i < NF4) ? lg4[i]
                             : make_float4(-1e30f, -1e30f, -1e30f, -1e30f);
        }
        #pragma unroll
        for (int u = 0; u < 4; ++u) {
            int i = i0 + u * NTHREADS;
            float xs[4] = {v[u].x, v[u].y, v[u].z, v[u].w};
            #pragma unroll
            for (int j = 0; j < 4; ++j) {
                bool pred = (fkey(xs[j]) >= cut) && (i < NF4);
                unsigned m = __ballot_sync(0xffffffffu, pred);
                if (m) {
                    if (pred) {
                        unsigned p = wcnt + (unsigned)__popc(m & lmask);
                        if (p < WSEG)
                            cand[wbase + p] =
                                ((unsigned long long)__float_as_uint(xs[j]) << 32)
                                | (unsigned)(i * 4 + j);
                    }
                    wcnt += (unsigned)__popc(m);
                }
            }
        }
    }
    if (lane == 0) wcnts[wid] = min(wcnt, (unsigned)WSEG);
    __syncthreads();

    // ---------------- Phase 2: sigmoid composite + refine histogram.
    // Composite = (f32 sigmoid bits << 32) | ~index : matches jax.lax.top_k
    // (sigmoid in double rounded to f32; ties break toward lower index).
    #pragma unroll 1
    for (unsigned s = tid; s < CAP; s += NTHREADS) {
        if ((s & (WSEG - 1)) < wcnts[s >> 8]) {
            unsigned long long cc = cand[s];
            float x = __uint_as_float((unsigned)(cc >> 32));
            unsigned idx = (unsigned)cc;
            float sf = (float)(1.0 / (1.0 + exp(-(double)x)));
            unsigned sb = __float_as_uint(sf);
            cand[s] = ((unsigned long long)sb << 32) | (~idx);
            atomicAdd(&hist[sig_bucket(sb)], 1u);
        }
    }
    __syncthreads();

    // ---------------- Phase 2b: exact-bucket rank-300 cut (tie-atomic:
    // equal-sigmoid candidates share a bucket, so inclusion can't split ties).
    if (tid < 32) scan_rank(hist, KSEL, &s_cutb, tid);
    __syncthreads();
    const unsigned cutb2 = s_cutb;

    // ---------------- Phase 3: refined compaction (warp-aggregated atomics).
    #pragma unroll 1
    for (unsigned s = tid; s < CAP; s += NTHREADS) {
        unsigned long long cc = 0;
        bool pred = false;
        if ((s & (WSEG - 1)) < wcnts[s >> 8]) {
            cc = cand[s];
            pred = sig_bucket((unsigned)(cc >> 32)) <= cutb2;
        }
        unsigned m = __ballot_sync(0xffffffffu, pred);
        if (m) {
            int leader = __ffs(m) - 1;
            unsigned p0 = 0;
            if (lane == leader) p0 = atomicAdd(&s_cnt2, (unsigned)__popc(m));
            p0 = __shfl_sync(0xffffffffu, p0, leader);
            if (pred) {
                unsigned p = p0 + (unsigned)__popc(m & lmask);
                if (p < CAP2) cand2[p] = cc;
            }
        }
    }
    __syncthreads();
    const unsigned cnt2 = min(s_cnt2, (unsigned)CAP2);

    // ---------------- Phase 4: bitonic sort (descending), hybrid syncs.
    unsigned M = 512; while (M < cnt2) M <<= 1;
    for (unsigned i = cnt2 + tid; i < M; i += NTHREADS) cand2[i] = 0ull;
    __syncthreads();
    const bool wok = (M <= (unsigned)NTHREADS);
    for (unsigned k = 2; k <= M; k <<= 1) {
        for (unsigned j = k >> 1; j > 0; j >>= 1) {
            for (unsigned i = tid; i < M; i += NTHREADS) {
                unsigned ixj = i ^ j;
                if (ixj > i) {
                    unsigned long long a = cand2[i], c = cand2[ixj];
                    bool up = ((i & k) == 0);
                    if (up ? (a < c) : (a > c)) { cand2[i] = c; cand2[ixj] = a; }
                }
            }
            unsigned jn = (j > 1) ? (j >> 1) : k;
            if (!wok || j >= 32 || jn >= 32) __syncthreads();
            else __syncwarp();
        }
    }

    // ---------------- Phase 5: emit top-300 (labels | boxes | scores).
    if (tid < KSEL) {
        unsigned long long cc = cand2[tid];
        unsigned sig = (unsigned)(cc >> 32);
        unsigned idx = ~(unsigned)cc;
        if (idx >= QC) idx = 0;                 // safety (unreachable)
        unsigned q   = idx / CDIM;
        unsigned cls = idx - q * CDIM;

        float4 bx = ((const float4*)boxes)[(size_t)b * QDIM + q];
        float W = sizes[2 * b], H = sizes[2 * b + 1];

        int BK = B * KSEL;
        int o  = b * KSEL + tid;
        out[o] = (float)cls;                                   // labels
        float x1 = (bx.x - 0.5f * bx.z) * W;
        float y1 = (bx.y - 0.5f * bx.w) * H;
        float x2 = (bx.x + 0.5f * bx.z) * W;
        float y2 = (bx.y + 0.5f * bx.w) * H;
        ((float4*)(out + BK))[o] = make_float4(x1, y1, x2, y2); // boxes
        out[5 * BK + o] = __uint_as_float(sig);                 // scores
    }
}

extern "C" void kernel_launch(void* const* d_in, const int* in_sizes, int n_in,
                              void* d_out, int out_size) {
    const float* logits = (const float*)d_in[0];
    const float* boxes  = (const float*)d_in[1];
    const float* sizes  = (const float*)d_in[2];
    int B = in_sizes[0] / QC;
    rtdetr_post_kernel<<<B, NTHREADS>>>(logits, boxes, sizes, (float*)d_out, B);
}

// round 10
// speedup vs baseline: 4.0040x; 1.7256x over previous
#include <cuda_runtime.h>
#include <math.h>

#define QDIM 1000
#define CDIM 80
#define QC   80000
#define NF4  (QC / 4)       // 20000
#define KSEL 300
#define NTHREADS 1024
#define NWARP 32
#define WSEG 256            // slots per warp segment (worst-case mean ~115)
#define CAP  (NWARP * WSEG) // 8192
#define CAP2 2048
#define SAMP_RANK 40
#define NBIN 2048

// Monotone order-preserving map f32 -> u32 (total order, handles negatives).
__device__ __forceinline__ unsigned fkey(float x) {
    unsigned u = __float_as_uint(x);
    return u ^ (((unsigned)((int)u >> 31)) | 0x80000000u);
}

// warp-0 segmented scan over hist[2048]: smallest bucket with cumcount>=rank.
__device__ __forceinline__ void scan_rank(const unsigned* hist, unsigned rank,
                                          unsigned* out_bucket, int lane) {
    unsigned s = 0;
    #pragma unroll 1
    for (int i = 0; i < 64; ++i)
        s += hist[lane * 64 + ((i + lane) & 63)];
    unsigned sc = s;
    #pragma unroll
    for (int o = 1; o < 32; o <<= 1) {
        unsigned t = __shfl_up_sync(0xffffffffu, sc, o);
        if (lane >= o) sc += t;
    }
    unsigned vote = __ballot_sync(0xffffffffu, sc >= rank);
    int seg = vote ? (__ffs(vote) - 1) : 31;
    if (lane == seg) {
        unsigned excl = sc - s;
        int cb = seg * 64 + 63;
        for (int i = seg * 64; i < seg * 64 + 64; ++i) {
            excl += hist[i];
            if (excl >= rank) { cb = i; break; }
        }
        *out_bucket = (unsigned)cb;
    }
}

__global__ void __launch_bounds__(NTHREADS, 2)
rtdetr_post_kernel(const float* __restrict__ logits,
                   const float* __restrict__ boxes,
                   const float* __restrict__ sizes,
                   float* __restrict__ out, int B)
{
    __shared__ unsigned long long cand[CAP];    // 64 KB, per-warp segments
    __shared__ unsigned long long cand2[CAP2];  // 16 KB
    __shared__ unsigned hist[NBIN];             //  8 KB
    __shared__ unsigned wcnts[NWARP];
    __shared__ unsigned s_cutb, s_cnt2;

    const int b    = blockIdx.x;
    const int tid  = threadIdx.x;
    const int wid  = tid >> 5;
    const int lane = tid & 31;
    const float* lg = logits + (size_t)b * QC;

    // ---------------- Phase 0a: sampled histogram of fkey top-11-bits.
    hist[tid] = 0; hist[tid + NTHREADS] = 0;
    if (tid == 0) s_cnt2 = 0;
    __syncthreads();
    // 16 coalesced runs of 128 consecutive floats (iid data -> valid sample)
    {
        int pos0 = (tid >> 7) * 5000 + (tid & 127);
        int s2   = tid + NTHREADS;
        int pos1 = (s2 >> 7) * 5000 + (s2 & 127);
        atomicAdd(&hist[2047u - (fkey(__ldg(lg + pos0)) >> 21)], 1u);
        atomicAdd(&hist[2047u - (fkey(__ldg(lg + pos1)) >> 21)], 1u);
    }
    __syncthreads();

    // ---------------- Phase 0b: rough cut = ~rank-40-of-2048 sample.
    // Coarse bucket edges: worst-case true survivors ~3700/batch (~115/warp);
    // WSEG=256 is ~13 sigma against per-warp overflow.
    if (tid < 32) scan_rank(hist, SAMP_RANK, &s_cutb, tid);
    __syncthreads();
    const unsigned cut = (2047u - s_cutb) << 21;   // keys >= cut survive
    hist[tid] = 0; hist[tid + NTHREADS] = 0;       // re-zero for refine pass

    // ---------------- Phase 1: stream. Zero atomics: per-warp segment in
    // cand[] + uniform register count, ballot/popc compaction. Loads are
    // explicitly batched (4x LDG.128) before any convergence point -> MLP=4.
    // Stores (logit_bits << 32) | idx  (NO sigmoid yet).
    const float4* lg4 = (const float4*)lg;
    const unsigned wbase = (unsigned)wid * WSEG;
    const unsigned lmask = (1u << lane) - 1u;
    unsigned wcnt = 0;                              // uniform across warp
    #pragma unroll 1
    for (int it = 0; it < 5; ++it) {
        int i0 = it * (4 * NTHREADS) + tid;
        float4 v[4];
        #pragma unroll
        for (int u = 0; u < 4; ++u) {
            int i = i0 + u * NTHREADS;
            v[u] = (i < NF4) ? lg4[i]
                             : make_float4(-1e30f, -1e30f, -1e30f, -1e30f);
        }
        #pragma unroll
        for (int u = 0; u < 4; ++u) {
            int i = i0 + u * NTHREADS;
            float xs[4] = {v[u].x, v[u].y, v[u].z, v[u].w};
            #pragma unroll
            for (int j = 0; j < 4; ++j) {
                bool pred = (fkey(xs[j]) >= cut) && (i < NF4);
                unsigned m = __ballot_sync(0xffffffffu, pred);
                if (m) {
                    if (pred) {
                        unsigned p = wcnt + (unsigned)__popc(m & lmask);
                        if (p < WSEG)
                            cand[wbase + p] =
                                ((unsigned long long)__float_as_uint(xs[j]) << 32)
                                | (unsigned)(i * 4 + j);
                    }
                    wcnt += (unsigned)__popc(m);
                }
            }
        }
    }
    if (lane == 0) wcnts[wid] = min(wcnt, (unsigned)WSEG);
    __syncthreads();

    // ---------------- Phase 2: refine histogram on LOGIT fkeys (no sigmoid).
    // Fine buckets of 2^14 logit-ulps (~4e-3 logit width near the cut), far
    // wider than any f32-sigmoid tie group (~1.3e-6) -> a +2-bucket margin
    // provably includes every exact-top-300 member incl. boundary tie groups.
    #pragma unroll 1
    for (unsigned s = tid; s < CAP; s += NTHREADS) {
        if ((s & (WSEG - 1)) < wcnts[s >> 8]) {
            unsigned fk = (unsigned)(cand[s] >> 32);
            fk = fkey(__uint_as_float(fk));
            unsigned d = (fk - cut) >> 14;
            atomicAdd(&hist[2047u - min(d, 2047u)], 1u);
        }
    }
    __syncthreads();

    // ---------------- Phase 2b: rank-300 cut over fine logit buckets.
    if (tid < 32) scan_rank(hist, KSEL, &s_cutb, tid);
    __syncthreads();
    const unsigned cutb2 = min(s_cutb + 2u, 2047u);   // +2 margin (safe)

    // ---------------- Phase 3: refined compaction (~300-400 survivors).
    #pragma unroll 1
    for (unsigned s = tid; s < CAP; s += NTHREADS) {
        unsigned long long cc = 0;
        bool pred = false;
        if ((s & (WSEG - 1)) < wcnts[s >> 8]) {
            cc = cand[s];
            unsigned fk = fkey(__uint_as_float((unsigned)(cc >> 32)));
            pred = (2047u - min((fk - cut) >> 14, 2047u)) <= cutb2;
        }
        unsigned m = __ballot_sync(0xffffffffu, pred);
        if (m) {
            int leader = __ffs(m) - 1;
            unsigned p0 = 0;
            if (lane == leader) p0 = atomicAdd(&s_cnt2, (unsigned)__popc(m));
            p0 = __shfl_sync(0xffffffffu, p0, leader);
            if (pred) {
                unsigned p = p0 + (unsigned)__popc(m & lmask);
                if (p < CAP2) cand2[p] = cc;
            }
        }
    }
    __syncthreads();
    const unsigned cnt2 = min(s_cnt2, (unsigned)CAP2);

    // ---------------- Phase 3b: exact sigmoid composite, survivors only.
    // Composite = (f32 sigmoid bits << 32) | ~index : matches jax.lax.top_k
    // (sigmoid in double rounded to f32; ties break toward lower index).
    // Only ~350 FP64 exp's per CTA (was ~2500-3700).
    for (unsigned i = tid; i < cnt2; i += NTHREADS) {
        unsigned long long cc = cand2[i];
        float x = __uint_as_float((unsigned)(cc >> 32));
        unsigned idx = (unsigned)cc;
        float sf = (float)(1.0 / (1.0 + exp(-(double)x)));
        cand2[i] = ((unsigned long long)__float_as_uint(sf) << 32) | (~idx);
    }
    __syncthreads();

    // ---------------- Phase 4: bitonic sort (descending), hybrid syncs.
    unsigned M = 512; while (M < cnt2) M <<= 1;
    for (unsigned i = cnt2 + tid; i < M; i += NTHREADS) cand2[i] = 0ull;
    __syncthreads();
    const bool wok = (M <= (unsigned)NTHREADS);
    for (unsigned k = 2; k <= M; k <<= 1) {
        for (unsigned j = k >> 1; j > 0; j >>= 1) {
            for (unsigned i = tid; i < M; i += NTHREADS) {
                unsigned ixj = i ^ j;
                if (ixj > i) {
                    unsigned long long a = cand2[i], c = cand2[ixj];
                    bool up = ((i & k) == 0);
                    if (up ? (a < c) : (a > c)) { cand2[i] = c; cand2[ixj] = a; }
                }
            }
            unsigned jn = (j > 1) ? (j >> 1) : k;
            if (!wok || j >= 32 || jn >= 32) __syncthreads();
            else __syncwarp();
        }
    }

    // ---------------- Phase 5: emit top-300 (labels | boxes | scores).
    if (tid < KSEL) {
        unsigned long long cc = cand2[tid];
        unsigned sig = (unsigned)(cc >> 32);
        unsigned idx = ~(unsigned)cc;
        if (idx >= QC) idx = 0;                 // safety (unreachable)
        unsigned q   = idx / CDIM;
        unsigned cls = idx - q * CDIM;

        float4 bx = ((const float4*)boxes)[(size_t)b * QDIM + q];
        float W = sizes[2 * b], H = sizes[2 * b + 1];

        int BK = B * KSEL;
        int o  = b * KSEL + tid;
        out[o] = (float)cls;                                   // labels
        float x1 = (bx.x - 0.5f * bx.z) * W;
        float y1 = (bx.y - 0.5f * bx.w) * H;
        float x2 = (bx.x + 0.5f * bx.z) * W;
        float y2 = (bx.y + 0.5f * bx.w) * H;
        ((float4*)(out + BK))[o] = make_float4(x1, y1, x2, y2); // boxes
        out[5 * BK + o] = __uint_as_float(sig);                 // scores
    }
}

extern "C" void kernel_launch(void* const* d_in, const int* in_sizes, int n_in,
                              void* d_out, int out_size) {
    const float* logits = (const float*)d_in[0];
    const float* boxes  = (const float*)d_in[1];
    const float* sizes  = (const float*)d_in[2];
    int B = in_sizes[0] / QC;
    rtdetr_post_kernel<<<B, NTHREADS>>>(logits, boxes, sizes, (float*)d_out, B);
}